// round 12
// baseline (speedup 1.0000x reference)
#include <cuda_runtime.h>
#include <cuda_bf16.h>

// GNN_Attention: N=50000, E=800000, IN=8, ED=2, H=2, C=64, HID=64, OUT=2
#define MAXN 50000
#define MAXE 800000
#define HC   128
#define HID  64
#define NEG_SLOPE 0.2f

// -------- static device scratch (16B aligned for float4 / red.v4) --------
__device__ __align__(16) float g_xl[MAXN * HC];
__device__ __align__(16) float g_xr[MAXN * HC];
__device__ __align__(16) float g_expl[MAXE * 2];    // (p0,p1) per SORTED edge
__device__ __align__(16) float g_denom[MAXN * 2];
__device__ __align__(16) float g_hacc[MAXN * HC];   // Σ p·xl[src]  (unnormalized)
__device__ __align__(16) float g_hw[MAXN * HID];    // (h @ gcn_W.T) * 1{n has in-edges}
__device__ __align__(16) float g_h2acc[MAXN * HID];

// dst-sorted edge arrays
__device__ int   g_cnt[MAXN + 1];
__device__ int   g_row[MAXN + 1];
__device__ int   g_rowcur[MAXN];
__device__ __align__(16) float4 g_es[MAXE];   // {src(bits), dst(bits), ea0, ea1}
__device__ int   g_es_eid[MAXE];

__device__ __forceinline__ void red_add_v4(float* p, float4 v) {
    asm volatile("red.global.add.v4.f32 [%0], {%1,%2,%3,%4};"
                 :: "l"(p), "f"(v.x), "f"(v.y), "f"(v.z), "f"(v.w)
                 : "memory");
}
__device__ __forceinline__ void red_add_v2(float* p, float a, float b) {
    asm volatile("red.global.add.v2.f32 [%0], {%1,%2};"
                 :: "l"(p), "f"(a), "f"(b)
                 : "memory");
}

// -------- 1. node projections + zero accumulators + zero hist --------
__global__ void k_proj(const float* __restrict__ x,
                       const float* __restrict__ Wl, const float* __restrict__ bl,
                       const float* __restrict__ Wr, const float* __restrict__ br,
                       int N) {
    int idx = blockIdx.x * blockDim.x + threadIdx.x;
    if (idx >= N * HC) return;
    g_hacc[idx] = 0.f;
    if (idx < N * HID) g_h2acc[idx] = 0.f;
    if (idx < N * 2)   g_denom[idx] = 0.f;
    if (idx < N + 1)   g_cnt[idx]   = 0;

    int n = idx >> 7, ch = idx & 127;
    const float* xv = x + n * 8;
    float sl = bl[ch], sr = br[ch];
    #pragma unroll
    for (int i = 0; i < 8; i++) {
        float xi = xv[i];
        sl += xi * Wl[ch * 8 + i];
        sr += xi * Wr[ch * 8 + i];
    }
    g_xl[idx] = sl;
    g_xr[idx] = sr;
}

// -------- 2. histogram of dst (2 edges/thread) --------
__global__ void k_hist(const int* __restrict__ ei, int E) {
    int t = blockIdx.x * blockDim.x + threadIdx.x;
    int e0 = t * 2;
    if (e0 >= E) return;
    int d0 = ei[E + e0];
    int d1 = (e0 + 1 < E) ? ei[E + e0 + 1] : -1;
    atomicAdd(&g_cnt[d0], 1);
    if (d1 >= 0) atomicAdd(&g_cnt[d1], 1);
}

// -------- 3. exclusive scan -> row offsets (single block) --------
__global__ void k_scan(int N) {
    __shared__ int wsum[32];
    int t = threadIdx.x;              // 1024
    int nb = blockDim.x;
    int CH = (N + nb - 1) / nb;
    int lo = t * CH, hi = min(lo + CH, N);
    int s = 0;
    for (int i = lo; i < hi; i++) s += g_cnt[i];
    int lane = t & 31, wid = t >> 5;
    int v = s;
    #pragma unroll
    for (int o = 1; o < 32; o <<= 1) {
        int u = __shfl_up_sync(0xffffffffu, v, o);
        if (lane >= o) v += u;
    }
    if (lane == 31) wsum[wid] = v;
    __syncthreads();
    if (wid == 0) {
        int xv = wsum[lane];
        #pragma unroll
        for (int o = 1; o < 32; o <<= 1) {
            int u = __shfl_up_sync(0xffffffffu, xv, o);
            if (lane >= o) xv += u;
        }
        wsum[lane] = xv;
    }
    __syncthreads();
    int excl = v - s + (wid > 0 ? wsum[wid - 1] : 0);
    int run = excl;
    for (int i = lo; i < hi; i++) {
        g_row[i] = run;
        g_rowcur[i] = run;
        run += g_cnt[i];
    }
    if (hi == N) g_row[N] = run;
}

// -------- 4. scatter edges into dst-sorted order (2 edges/thread) --------
__global__ void k_scatter(const int* __restrict__ ei,
                          const float* __restrict__ ea, int E) {
    int t = blockIdx.x * blockDim.x + threadIdx.x;
    int e0 = t * 2;
    if (e0 >= E) return;
    int e1 = min(e0 + 1, E - 1);
    int s0 = ei[e0],      s1 = ei[e1];
    int d0 = ei[E + e0],  d1 = ei[E + e1];
    float2 a0 = ((const float2*)ea)[e0];
    float2 a1 = ((const float2*)ea)[e1];
    int p0 = atomicAdd(&g_rowcur[d0], 1);
    g_es[p0] = make_float4(__int_as_float(s0), __int_as_float(d0), a0.x, a0.y);
    g_es_eid[p0] = e0;
    if (e0 + 1 < E) {
        int p1 = atomicAdd(&g_rowcur[d1], 1);
        g_es[p1] = make_float4(__int_as_float(s1), __int_as_float(d1), a1.x, a1.y);
        g_es_eid[p1] = e0 + 1;
    }
}

// -------- 5. logits + exp + denom + message scatter on SORTED edges --------
// 4 consecutive sorted edges per warp; when all share a dst (common: avg
// degree 16), xr is loaded once and the 4 denom/hacc reds combine into 1.
__global__ void k_logits(const float* __restrict__ We,
                         const float* __restrict__ att, int E) {
    int warp = (blockIdx.x * blockDim.x + threadIdx.x) >> 5;
    int lane = threadIdx.x & 31;
    int e0 = warp * 4;
    if (e0 >= E) return;

    float4 at   = ((const float4*)att)[lane];
    float4 we01 = ((const float4*)We)[2 * lane];
    float4 we23 = ((const float4*)We)[2 * lane + 1];

    int src[4], dst[4];
    float2 eav[4];
    #pragma unroll
    for (int j = 0; j < 4; j++) {
        float4 es = g_es[min(e0 + j, E - 1)];
        src[j] = __float_as_int(es.x);
        dst[j] = __float_as_int(es.y);
        eav[j] = make_float2(es.z, es.w);
    }
    bool uni = (e0 + 3 < E) && (dst[0] == dst[3]);

    float4 a[4];
    #pragma unroll
    for (int j = 0; j < 4; j++) a[j] = ((const float4*)g_xl)[src[j] * 32 + lane];
    float4 b[4];
    if (uni) {
        b[0] = ((const float4*)g_xr)[dst[0] * 32 + lane];
        b[1] = b[0]; b[2] = b[0]; b[3] = b[0];
    } else {
        #pragma unroll
        for (int j = 0; j < 4; j++) b[j] = ((const float4*)g_xr)[dst[j] * 32 + lane];
    }

    float s[4];
    #pragma unroll
    for (int j = 0; j < 4; j++) {
        float e_0 = we01.x * eav[j].x + we01.y * eav[j].y;
        float e_1 = we01.z * eav[j].x + we01.w * eav[j].y;
        float e_2 = we23.x * eav[j].x + we23.y * eav[j].y;
        float e_3 = we23.z * eav[j].x + we23.w * eav[j].y;
        float z, acc = 0.f;
        z = a[j].x + b[j].x + e_0; z = z > 0.f ? z : NEG_SLOPE * z; acc += z * at.x;
        z = a[j].y + b[j].y + e_1; z = z > 0.f ? z : NEG_SLOPE * z; acc += z * at.y;
        z = a[j].z + b[j].z + e_2; z = z > 0.f ? z : NEG_SLOPE * z; acc += z * at.z;
        z = a[j].w + b[j].w + e_3; z = z > 0.f ? z : NEG_SLOPE * z; acc += z * at.w;
        s[j] = acc;
    }
    #pragma unroll
    for (int o = 8; o >= 1; o >>= 1) {
        #pragma unroll
        for (int j = 0; j < 4; j++)
            s[j] += __shfl_xor_sync(0xffffffffu, s[j], o, 16);
    }
    float p[4], pd[4];
    #pragma unroll
    for (int j = 0; j < 4; j++) p[j] = __expf(s[j]);  // |logit| small: no max-sub
    #pragma unroll
    for (int j = 0; j < 4; j++) pd[j] = __shfl_down_sync(0xffffffffu, p[j], 16);

    // expl writes: lanes 0-3, one sorted-edge each
    if (lane < 4) {
        float myp  = (lane == 0) ? p[0]  : (lane == 1) ? p[1]  : (lane == 2) ? p[2]  : p[3];
        float mypd = (lane == 0) ? pd[0] : (lane == 1) ? pd[1] : (lane == 2) ? pd[2] : pd[3];
        int e = e0 + lane;
        if (e < E) ((float2*)g_expl)[e] = make_float2(myp, mypd);
    }
    if (uni) {
        if (lane == 0)
            red_add_v2(&g_denom[2 * dst[0]],
                       p[0] + p[1] + p[2] + p[3], pd[0] + pd[1] + pd[2] + pd[3]);
        float4 m;
        m.x = p[0] * a[0].x + p[1] * a[1].x + p[2] * a[2].x + p[3] * a[3].x;
        m.y = p[0] * a[0].y + p[1] * a[1].y + p[2] * a[2].y + p[3] * a[3].y;
        m.z = p[0] * a[0].z + p[1] * a[1].z + p[2] * a[2].z + p[3] * a[3].z;
        m.w = p[0] * a[0].w + p[1] * a[1].w + p[2] * a[2].w + p[3] * a[3].w;
        red_add_v4(&g_hacc[dst[0] * HC + lane * 4], m);
    } else {
        if (lane < 4) {
            float myp  = (lane == 0) ? p[0]  : (lane == 1) ? p[1]  : (lane == 2) ? p[2]  : p[3];
            float mypd = (lane == 0) ? pd[0] : (lane == 1) ? pd[1] : (lane == 2) ? pd[2] : pd[3];
            int   myd  = (lane == 0) ? dst[0]: (lane == 1) ? dst[1]: (lane == 2) ? dst[2]: dst[3];
            if (e0 + lane < E) red_add_v2(&g_denom[2 * myd], myp, mypd);
        }
        #pragma unroll
        for (int j = 0; j < 4; j++) {
            if (e0 + j < E) {
                float4 m = a[j];
                m.x *= p[j]; m.y *= p[j]; m.z *= p[j]; m.w *= p[j];
                red_add_v4(&g_hacc[dst[j] * HC + lane * 4], m);
            }
        }
    }
}

// -------- 6. register-tiled node GEMM (unchanged) --------
#define NHB 64
#define WP  68
__global__ void k_node_hw(const float* __restrict__ gat_bias,
                          const float* __restrict__ gcn_W, int N) {
    __shared__ __align__(16) float Wsh[64 * WP];
    __shared__ __align__(16) float hsh[64 * WP];
    __shared__ float inv0[NHB], inv1[NHB], dsh[NHB];
    __shared__ float bsh[HC];
    int t = threadIdx.x;
    int base = blockIdx.x * NHB;

    if (t < HC) bsh[t] = gat_bias[t];
    if (t < NHB) {
        int n = base + t;
        if (n < N) {
            float2 dn = ((const float2*)g_denom)[n];
            inv0[t] = dn.x > 0.f ? __fdividef(1.f, dn.x) : 0.f;
            inv1[t] = dn.y > 0.f ? __fdividef(1.f, dn.y) : 0.f;
            dsh[t]  = dn.x > 0.f ? 1.f : 0.f;
        } else { inv0[t] = 0.f; inv1[t] = 0.f; dsh[t] = 0.f; }
    }
    __syncthreads();

    int tx = t & 15;
    int ty = t >> 4;
    float acc[4][4];
    #pragma unroll
    for (int i = 0; i < 4; i++)
        #pragma unroll
        for (int j = 0; j < 4; j++) acc[i][j] = 0.f;

    #pragma unroll
    for (int ph = 0; ph < 2; ph++) {
        {
            int k = t & 63, cb = t >> 6;
            #pragma unroll
            for (int j = 0; j < 16; j++) {
                int c = cb + j * 4;
                Wsh[k * WP + c] = gcn_W[c * HC + ph * 64 + k];
            }
        }
        {
            int c = t & 63, nb = t >> 6;
            #pragma unroll
            for (int j = 0; j < 16; j++) {
                int nl = nb + j * 4;
                int n = base + nl;
                float v = 0.f;
                if (n < N) {
                    float iv = ph ? inv1[nl] : inv0[nl];
                    v = fmaxf(g_hacc[n * HC + ph * 64 + c] * iv + bsh[ph * 64 + c], 0.f);
                }
                hsh[c * WP + nl] = v;
            }
        }
        __syncthreads();
        #pragma unroll 4
        for (int k = 0; k < 64; k++) {
            float4 w = *(const float4*)&Wsh[k * WP + tx * 4];
            float4 h = *(const float4*)&hsh[k * WP + ty * 4];
            acc[0][0] += h.x * w.x; acc[0][1] += h.x * w.y;
            acc[0][2] += h.x * w.z; acc[0][3] += h.x * w.w;
            acc[1][0] += h.y * w.x; acc[1][1] += h.y * w.y;
            acc[1][2] += h.y * w.z; acc[1][3] += h.y * w.w;
            acc[2][0] += h.z * w.x; acc[2][1] += h.z * w.y;
            acc[2][2] += h.z * w.z; acc[2][3] += h.z * w.w;
            acc[3][0] += h.w * w.x; acc[3][1] += h.w * w.y;
            acc[3][2] += h.w * w.z; acc[3][3] += h.w * w.w;
        }
        __syncthreads();
    }
    #pragma unroll
    for (int i = 0; i < 4; i++) {
        int nl = ty * 4 + i;
        int n = base + nl;
        if (n < N) {
            float di = dsh[nl];
            float4 o = make_float4(acc[i][0] * di, acc[i][1] * di,
                                   acc[i][2] * di, acc[i][3] * di);
            ((float4*)g_hw)[n * 16 + tx] = o;
        }
    }
}

// -------- 7. alpha + GCN scatter on SORTED edges (combined reds) --------
// Half-warp (16 lanes) handles 4 consecutive sorted edges.
__global__ void k_gcn_edge(float* __restrict__ alpha_out, int E) {
    int warp = (blockIdx.x * blockDim.x + threadIdx.x) >> 5;
    int lane = threadIdx.x & 31;
    int half = lane >> 4;
    int l    = lane & 15;
    int e0 = warp * 8 + half * 4;   // 4 consecutive edges per half-warp
    if (e0 >= E) return;

    int src[4], dst[4];
    #pragma unroll
    for (int j = 0; j < 4; j++) {
        float4 es = g_es[min(e0 + j, E - 1)];
        src[j] = __float_as_int(es.x);
        dst[j] = __float_as_int(es.y);
    }
    bool uni = (e0 + 3 < E) && (dst[0] == dst[3]);

    float2 pe[4], dn[4];
    #pragma unroll
    for (int j = 0; j < 4; j++) pe[j] = ((const float2*)g_expl)[min(e0 + j, E - 1)];
    #pragma unroll
    for (int j = 0; j < 4; j++) dn[j] = ((const float2*)g_denom)[dst[j]];

    float nv[4];
    #pragma unroll
    for (int j = 0; j < 4; j++) {
        float a0 = __fdividef(pe[j].x, dn[j].x);
        float a1 = __fdividef(pe[j].y, dn[j].y);
        nv[j] = 0.5f * (a0 + a1);
        if (l == j && e0 + j < E) {       // lanes 0-3 write one alpha each
            int eid = g_es_eid[e0 + j];
            ((float2*)alpha_out)[eid] = make_float2(a0, a1);
        }
    }
    float4 v[4];
    #pragma unroll
    for (int j = 0; j < 4; j++)
        v[j] = ((const float4*)g_hw)[src[j] * 16 + l];

    if (uni) {
        float4 m;
        m.x = nv[0] * v[0].x + nv[1] * v[1].x + nv[2] * v[2].x + nv[3] * v[3].x;
        m.y = nv[0] * v[0].y + nv[1] * v[1].y + nv[2] * v[2].y + nv[3] * v[3].y;
        m.z = nv[0] * v[0].z + nv[1] * v[1].z + nv[2] * v[2].z + nv[3] * v[3].z;
        m.w = nv[0] * v[0].w + nv[1] * v[1].w + nv[2] * v[2].w + nv[3] * v[3].w;
        red_add_v4(&g_h2acc[dst[0] * HID + l * 4], m);
    } else {
        #pragma unroll
        for (int j = 0; j < 4; j++) {
            if (e0 + j < E) {
                float4 m = v[j];
                m.x *= nv[j]; m.y *= nv[j]; m.z *= nv[j]; m.w *= nv[j];
                red_add_v4(&g_h2acc[dst[j] * HID + l * 4], m);
            }
        }
    }
}

// -------- 8. per-node output --------
__global__ void k_node_out(const float* __restrict__ gcn_b,
                           const float* __restrict__ out_W,
                           const float* __restrict__ out_b,
                           float* __restrict__ out, int N) {
    int t = blockIdx.x * blockDim.x + threadIdx.x;
    int n = t >> 5;
    if (n >= N) return;
    int lane = t & 31;
    float2 hv = ((const float2*)g_h2acc)[n * 32 + lane];
    float h0 = fmaxf(hv.x + gcn_b[2 * lane],     0.f);
    float h1 = fmaxf(hv.y + gcn_b[2 * lane + 1], 0.f);
    float s0 = h0 * out_W[2 * lane]      + h1 * out_W[2 * lane + 1];
    float s1 = h0 * out_W[64 + 2 * lane] + h1 * out_W[64 + 2 * lane + 1];
    #pragma unroll
    for (int o = 16; o >= 1; o >>= 1) {
        s0 += __shfl_down_sync(0xffffffffu, s0, o);
        s1 += __shfl_down_sync(0xffffffffu, s1, o);
    }
    if (lane == 0) {
        out[2 * n]     = s0 + out_b[0];
        out[2 * n + 1] = s1 + out_b[1];
    }
}

extern "C" void kernel_launch(void* const* d_in, const int* in_sizes, int n_in,
                              void* d_out, int out_size) {
    const float* x        = (const float*)d_in[0];
    const float* ea       = (const float*)d_in[1];
    const int*   ei       = (const int*)d_in[2];   // int32 (JAX x64 disabled)
    const float* Wl       = (const float*)d_in[3];
    const float* bl       = (const float*)d_in[4];
    const float* Wr       = (const float*)d_in[5];
    const float* br       = (const float*)d_in[6];
    const float* We       = (const float*)d_in[7];
    const float* att      = (const float*)d_in[8];
    const float* gat_bias = (const float*)d_in[9];
    const float* gcn_W    = (const float*)d_in[10];
    const float* gcn_b    = (const float*)d_in[11];
    const float* out_W    = (const float*)d_in[12];
    const float* out_b    = (const float*)d_in[13];

    int N = in_sizes[0] / 8;     // IN=8
    int E = in_sizes[1] / 2;     // ED=2

    float* out       = (float*)d_out;
    float* alpha_out = (float*)d_out + (size_t)N * 2;

    const int NT = 256;
    int warpsL = (E + 3) / 4;   // 4 edges/warp
    int warpsG = (E + 7) / 8;   // 8 edges/warp
    k_proj<<<(N * HC + NT - 1) / NT, NT>>>(x, Wl, bl, Wr, br, N);
    k_hist<<<(E / 2 + NT - 1) / NT, NT>>>(ei, E);
    k_scan<<<1, 1024>>>(N);
    k_scatter<<<(E / 2 + NT - 1) / NT, NT>>>(ei, ea, E);
    k_logits<<<(int)(((size_t)warpsL * 32 + NT - 1) / NT), NT>>>(We, att, E);
    k_node_hw<<<(N + NHB - 1) / NHB, 256>>>(gat_bias, gcn_W, N);
    k_gcn_edge<<<(int)(((size_t)warpsG * 32 + NT - 1) / NT), NT>>>(alpha_out, E);
    k_node_out<<<(int)(((size_t)N * 32 + NT - 1) / NT), NT>>>(gcn_b, out_W, out_b, out, N);
}

// round 13
// speedup vs baseline: 1.3158x; 1.3158x over previous
#include <cuda_runtime.h>
#include <cuda_fp16.h>
#include <cuda_bf16.h>

// GNN_Attention: N=50000, E=800000, IN=8, ED=2, H=2, C=64, HID=64, OUT=2
#define MAXN 50000
#define MAXE 800000
#define HC   128
#define HID  64
#define NEG_SLOPE 0.2f

// -------- static device scratch (16B aligned for float4 / red.v4) --------
__device__ __align__(16) float  g_xl[MAXN * HC];
__device__ __align__(16) __half g_xr[MAXN * HC];    // fp16: logit-only operand
__device__ __align__(16) float  g_expl[MAXE * 2];
__device__ __align__(16) float  g_denom[MAXN * 2];
__device__ __align__(16) float  g_hacc[MAXN * HC];  // Σ p·xl[src] (unnormalized)
__device__ __align__(16) float  g_hw[MAXN * HID];   // (h @ gcn_W.T) * 1{n has in-edges}
__device__ __align__(16) float  g_h2acc[MAXN * HID];

__device__ __forceinline__ void red_add_v4(float* p, float4 v) {
    asm volatile("red.global.add.v4.f32 [%0], {%1,%2,%3,%4};"
                 :: "l"(p), "f"(v.x), "f"(v.y), "f"(v.z), "f"(v.w)
                 : "memory");
}
__device__ __forceinline__ void red_add_v2(float* p, float a, float b) {
    asm volatile("red.global.add.v2.f32 [%0], {%1,%2};"
                 :: "l"(p), "f"(a), "f"(b)
                 : "memory");
}

// -------- 1. node projections + zero all accumulators (fused) --------
__global__ void k_proj(const float* __restrict__ x,
                       const float* __restrict__ Wl, const float* __restrict__ bl,
                       const float* __restrict__ Wr, const float* __restrict__ br,
                       int N) {
    int idx = blockIdx.x * blockDim.x + threadIdx.x;
    if (idx >= N * HC) return;
    g_hacc[idx] = 0.f;
    if (idx < N * HID) g_h2acc[idx] = 0.f;
    if (idx < N * 2)   g_denom[idx] = 0.f;

    int n = idx >> 7, ch = idx & 127;
    const float* xv = x + n * 8;
    float sl = bl[ch], sr = br[ch];
    #pragma unroll
    for (int i = 0; i < 8; i++) {
        float xi = xv[i];
        sl += xi * Wl[ch * 8 + i];
        sr += xi * Wr[ch * 8 + i];
    }
    g_xl[idx] = sl;
    g_xr[idx] = __float2half(sr);
}

// -------- 2. fused logits + exp + denom + unnormalized message scatter ------
__global__ void k_logits(const int* __restrict__ ei,
                         const float* __restrict__ ea,
                         const float* __restrict__ We,
                         const float* __restrict__ att, int E) {
    int warp = (blockIdx.x * blockDim.x + threadIdx.x) >> 5;
    int lane = threadIdx.x & 31;
    int e0 = warp * 4;
    if (e0 >= E) return;

    float4 at   = ((const float4*)att)[lane];
    float4 we01 = ((const float4*)We)[2 * lane];
    float4 we23 = ((const float4*)We)[2 * lane + 1];

    int src[4], dst[4];
    float2 eav[4];
    #pragma unroll
    for (int j = 0; j < 4; j++) {
        int e = min(e0 + j, E - 1);
        src[j] = ei[e];
        dst[j] = ei[E + e];
        eav[j] = ((const float2*)ea)[e];
    }
    float4 a[4];
    #pragma unroll
    for (int j = 0; j < 4; j++) a[j] = ((const float4*)g_xl)[src[j] * 32 + lane];
    // xr in fp16: 4 halves = 8B per lane
    float4 b[4];
    #pragma unroll
    for (int j = 0; j < 4; j++) {
        __half2 h01 = ((const __half2*)g_xr)[src[0] * 0 + dst[j] * 64 + lane * 2];
        __half2 h23 = ((const __half2*)g_xr)[dst[j] * 64 + lane * 2 + 1];
        float2 f01 = __half22float2(h01);
        float2 f23 = __half22float2(h23);
        b[j] = make_float4(f01.x, f01.y, f23.x, f23.y);
    }

    float s[4];
    #pragma unroll
    for (int j = 0; j < 4; j++) {
        float e_0 = we01.x * eav[j].x + we01.y * eav[j].y;
        float e_1 = we01.z * eav[j].x + we01.w * eav[j].y;
        float e_2 = we23.x * eav[j].x + we23.y * eav[j].y;
        float e_3 = we23.z * eav[j].x + we23.w * eav[j].y;
        float z, acc = 0.f;
        z = a[j].x + b[j].x + e_0; z = z > 0.f ? z : NEG_SLOPE * z; acc += z * at.x;
        z = a[j].y + b[j].y + e_1; z = z > 0.f ? z : NEG_SLOPE * z; acc += z * at.y;
        z = a[j].z + b[j].z + e_2; z = z > 0.f ? z : NEG_SLOPE * z; acc += z * at.z;
        z = a[j].w + b[j].w + e_3; z = z > 0.f ? z : NEG_SLOPE * z; acc += z * at.w;
        s[j] = acc;
    }
    #pragma unroll
    for (int o = 8; o >= 1; o >>= 1) {
        #pragma unroll
        for (int j = 0; j < 4; j++)
            s[j] += __shfl_xor_sync(0xffffffffu, s[j], o, 16);
    }
    float p[4], pd[4];
    #pragma unroll
    for (int j = 0; j < 4; j++) p[j] = __expf(s[j]);  // |logit| small: no max-sub
    #pragma unroll
    for (int j = 0; j < 4; j++) pd[j] = __shfl_down_sync(0xffffffffu, p[j], 16);

    // epilogue distributed across lanes 0-3 (one edge each)
    if (lane < 4) {
        float myp  = (lane == 0) ? p[0]  : (lane == 1) ? p[1]  : (lane == 2) ? p[2]  : p[3];
        float mypd = (lane == 0) ? pd[0] : (lane == 1) ? pd[1] : (lane == 2) ? pd[2] : pd[3];
        int   myd  = (lane == 0) ? dst[0]: (lane == 1) ? dst[1]: (lane == 2) ? dst[2]: dst[3];
        int e = e0 + lane;
        if (e < E) {
            ((float2*)g_expl)[e] = make_float2(myp, mypd);
            red_add_v2(&g_denom[2 * myd], myp, mypd);
        }
    }
    #pragma unroll
    for (int j = 0; j < 4; j++) {
        if (e0 + j < E) {
            float4 m = a[j];
            m.x *= p[j]; m.y *= p[j]; m.z *= p[j]; m.w *= p[j];
            red_add_v4(&g_hacc[dst[j] * HC + lane * 4], m);
        }
    }
}

// -------- 3. register-tiled node GEMM: 64 nodes/block, 4x4 tile/thread ------
// g_hw = (relu(hacc/denom + bias) @ gcn_W.T) * 1{denom>0}
// (deg == 1 identically: softmax sums to 1 per head, so dinv is an indicator)
#define NHB 64
#define WP  68
__global__ void k_node_hw(const float* __restrict__ gat_bias,
                          const float* __restrict__ gcn_W, int N) {
    __shared__ __align__(16) float Wsh[64 * WP];   // 17.4 KB
    __shared__ __align__(16) float hsh[64 * WP];   // 17.4 KB
    __shared__ float inv0[NHB], inv1[NHB], dsh[NHB];
    __shared__ float bsh[HC];
    int t = threadIdx.x;                 // 256
    int base = blockIdx.x * NHB;

    if (t < HC) bsh[t] = gat_bias[t];
    if (t < NHB) {
        int n = base + t;
        if (n < N) {
            float2 dn = ((const float2*)g_denom)[n];
            inv0[t] = dn.x > 0.f ? __fdividef(1.f, dn.x) : 0.f;
            inv1[t] = dn.y > 0.f ? __fdividef(1.f, dn.y) : 0.f;
            dsh[t]  = dn.x > 0.f ? 1.f : 0.f;   // indicator(n has in-edges)
        } else { inv0[t] = 0.f; inv1[t] = 0.f; dsh[t] = 0.f; }
    }
    __syncthreads();

    int tx = t & 15;          // col group: cols 4tx..4tx+3
    int ty = t >> 4;          // node group: nodes 4ty..4ty+3
    float acc[4][4];
    #pragma unroll
    for (int i = 0; i < 4; i++)
        #pragma unroll
        for (int j = 0; j < 4; j++) acc[i][j] = 0.f;

    #pragma unroll
    for (int ph = 0; ph < 2; ph++) {
        {
            int k = t & 63, cb = t >> 6;
            #pragma unroll
            for (int j = 0; j < 16; j++) {
                int c = cb + j * 4;
                Wsh[k * WP + c] = gcn_W[c * HC + ph * 64 + k];
            }
        }
        {
            int c = t & 63, nb = t >> 6;
            #pragma unroll
            for (int j = 0; j < 16; j++) {
                int nl = nb + j * 4;
                int n = base + nl;
                float v = 0.f;
                if (n < N) {
                    float iv = ph ? inv1[nl] : inv0[nl];
                    v = fmaxf(g_hacc[n * HC + ph * 64 + c] * iv + bsh[ph * 64 + c], 0.f);
                }
                hsh[c * WP + nl] = v;
            }
        }
        __syncthreads();
        #pragma unroll 4
        for (int k = 0; k < 64; k++) {
            float4 w = *(const float4*)&Wsh[k * WP + tx * 4];
            float4 h = *(const float4*)&hsh[k * WP + ty * 4];
            acc[0][0] += h.x * w.x; acc[0][1] += h.x * w.y;
            acc[0][2] += h.x * w.z; acc[0][3] += h.x * w.w;
            acc[1][0] += h.y * w.x; acc[1][1] += h.y * w.y;
            acc[1][2] += h.y * w.z; acc[1][3] += h.y * w.w;
            acc[2][0] += h.z * w.x; acc[2][1] += h.z * w.y;
            acc[2][2] += h.z * w.z; acc[2][3] += h.z * w.w;
            acc[3][0] += h.w * w.x; acc[3][1] += h.w * w.y;
            acc[3][2] += h.w * w.z; acc[3][3] += h.w * w.w;
        }
        __syncthreads();
    }
    #pragma unroll
    for (int i = 0; i < 4; i++) {
        int nl = ty * 4 + i;
        int n = base + nl;
        if (n < N) {
            float di = dsh[nl];          // indicator fold (src-side GCN norm)
            float4 o = make_float4(acc[i][0] * di, acc[i][1] * di,
                                   acc[i][2] * di, acc[i][3] * di);
            ((float4*)g_hw)[n * 16 + tx] = o;
        }
    }
}

// -------- 4. fused alpha + GCN edge scatter --------
// alpha = expl/denom[dst]; ew = mean; h2acc[dst] += ew·hw[src]
// (dinv[dst] == 1 for every edge; dinv[src] indicator pre-folded into hw)
__global__ void k_gcn_edge(const int* __restrict__ ei,
                           float* __restrict__ alpha_out, int E) {
    int warp = (blockIdx.x * blockDim.x + threadIdx.x) >> 5;
    int lane = threadIdx.x & 31;
    int half = lane >> 4;
    int l    = lane & 15;
    int e0 = warp * 8 + half;
    if (e0 >= E) return;

    int src[4], dst[4];
    #pragma unroll
    for (int j = 0; j < 4; j++) {
        int e = min(e0 + 2 * j, E - 1);
        src[j] = ei[e];
        dst[j] = ei[E + e];
    }
    float2 pe[4];
    #pragma unroll
    for (int j = 0; j < 4; j++) pe[j] = ((const float2*)g_expl)[min(e0 + 2 * j, E - 1)];
    float2 dn[4];
    #pragma unroll
    for (int j = 0; j < 4; j++) dn[j] = ((const float2*)g_denom)[dst[j]];

    float nv[4];
    #pragma unroll
    for (int j = 0; j < 4; j++) {
        float a0 = __fdividef(pe[j].x, dn[j].x);
        float a1 = __fdividef(pe[j].y, dn[j].y);
        nv[j] = 0.5f * (a0 + a1);
        int e = e0 + 2 * j;
        if (l == 0 && e < E)
            ((float2*)alpha_out)[e] = make_float2(a0, a1);
    }
    float4 v[4];
    #pragma unroll
    for (int j = 0; j < 4; j++)
        v[j] = ((const float4*)g_hw)[src[j] * 16 + l];
    #pragma unroll
    for (int j = 0; j < 4; j++) {
        if (e0 + 2 * j < E) {
            float4 m = v[j];
            m.x *= nv[j]; m.y *= nv[j]; m.z *= nv[j]; m.w *= nv[j];
            red_add_v4(&g_h2acc[dst[j] * HID + l * 4], m);
        }
    }
}

// -------- 5. per-node output --------
__global__ void k_node_out(const float* __restrict__ gcn_b,
                           const float* __restrict__ out_W,
                           const float* __restrict__ out_b,
                           float* __restrict__ out, int N) {
    int t = blockIdx.x * blockDim.x + threadIdx.x;
    int n = t >> 5;
    if (n >= N) return;
    int lane = t & 31;
    float2 hv = ((const float2*)g_h2acc)[n * 32 + lane];
    float h0 = fmaxf(hv.x + gcn_b[2 * lane],     0.f);
    float h1 = fmaxf(hv.y + gcn_b[2 * lane + 1], 0.f);
    float s0 = h0 * out_W[2 * lane]      + h1 * out_W[2 * lane + 1];
    float s1 = h0 * out_W[64 + 2 * lane] + h1 * out_W[64 + 2 * lane + 1];
    #pragma unroll
    for (int o = 16; o >= 1; o >>= 1) {
        s0 += __shfl_down_sync(0xffffffffu, s0, o);
        s1 += __shfl_down_sync(0xffffffffu, s1, o);
    }
    if (lane == 0) {
        out[2 * n]     = s0 + out_b[0];
        out[2 * n + 1] = s1 + out_b[1];
    }
}

extern "C" void kernel_launch(void* const* d_in, const int* in_sizes, int n_in,
                              void* d_out, int out_size) {
    const float* x        = (const float*)d_in[0];
    const float* ea       = (const float*)d_in[1];
    const int*   ei       = (const int*)d_in[2];   // int32 (JAX x64 disabled)
    const float* Wl       = (const float*)d_in[3];
    const float* bl       = (const float*)d_in[4];
    const float* Wr       = (const float*)d_in[5];
    const float* br       = (const float*)d_in[6];
    const float* We       = (const float*)d_in[7];
    const float* att      = (const float*)d_in[8];
    const float* gat_bias = (const float*)d_in[9];
    const float* gcn_W    = (const float*)d_in[10];
    const float* gcn_b    = (const float*)d_in[11];
    const float* out_W    = (const float*)d_in[12];
    const float* out_b    = (const float*)d_in[13];

    int N = in_sizes[0] / 8;     // IN=8
    int E = in_sizes[1] / 2;     // ED=2

    float* out       = (float*)d_out;
    float* alpha_out = (float*)d_out + (size_t)N * 2;

    const int NT = 256;
    int warpsL = (E + 3) / 4;   // 4 edges/warp
    int warpsG = (E + 7) / 8;   // 8 edges/warp
    k_proj<<<(N * HC + NT - 1) / NT, NT>>>(x, Wl, bl, Wr, br, N);
    k_logits<<<(int)(((size_t)warpsL * 32 + NT - 1) / NT), NT>>>(ei, ea, We, att, E);
    k_node_hw<<<(N + NHB - 1) / NHB, 256>>>(gat_bias, gcn_W, N);
    k_gcn_edge<<<(int)(((size_t)warpsG * 32 + NT - 1) / NT), NT>>>(ei, alpha_out, E);
    k_node_out<<<(int)(((size_t)N * 32 + NT - 1) / NT), NT>>>(gcn_b, out_W, out_b, out, N);
}

// round 15
// speedup vs baseline: 1.3375x; 1.0165x over previous
#include <cuda_runtime.h>
#include <cuda_fp16.h>
#include <cuda_bf16.h>

// GNN_Attention: N=50000, E=800000, IN=8, ED=2, H=2, C=64, HID=64, OUT=2
#define MAXN 50000
#define MAXE 800000
#define HC   128
#define HID  64
#define NEG_SLOPE 0.2f

// -------- static device scratch --------
// Gather-side node tables in fp16 (halves edge-kernel read traffic);
// all accumulators stay fp32.
__device__ __align__(16) __half g_xl[MAXN * HC];
__device__ __align__(16) __half g_xr[MAXN * HC];
__device__ __align__(16) float  g_expl[MAXE * 2];
__device__ __align__(16) float  g_denom[MAXN * 2];
__device__ __align__(16) float  g_hacc[MAXN * HC];  // Σ p·xl[src] (fp32)
__device__ __align__(16) __half g_hw[MAXN * HID];   // (h @ gcn_W.T) * indicator
__device__ __align__(16) float  g_h2acc[MAXN * HID];

__device__ __forceinline__ void red_add_v4(float* p, float4 v) {
    asm volatile("red.global.add.v4.f32 [%0], {%1,%2,%3,%4};"
                 :: "l"(p), "f"(v.x), "f"(v.y), "f"(v.z), "f"(v.w)
                 : "memory");
}
__device__ __forceinline__ void red_add_v2(float* p, float a, float b) {
    asm volatile("red.global.add.v2.f32 [%0], {%1,%2};"
                 :: "l"(p), "f"(a), "f"(b)
                 : "memory");
}
__device__ __forceinline__ float4 ld_half4(const __half* base, int idx8) {
    uint2 raw = ((const uint2*)base)[idx8];
    __half2 h01 = *reinterpret_cast<__half2*>(&raw.x);
    __half2 h23 = *reinterpret_cast<__half2*>(&raw.y);
    float2 f01 = __half22float2(h01);
    float2 f23 = __half22float2(h23);
    return make_float4(f01.x, f01.y, f23.x, f23.y);
}

// -------- 1. node projections + zero all accumulators (fused) --------
__global__ void k_proj(const float* __restrict__ x,
                       const float* __restrict__ Wl, const float* __restrict__ bl,
                       const float* __restrict__ Wr, const float* __restrict__ br,
                       int N) {
    int idx = blockIdx.x * blockDim.x + threadIdx.x;
    if (idx >= N * HC) return;
    g_hacc[idx] = 0.f;
    if (idx < N * HID) g_h2acc[idx] = 0.f;
    if (idx < N * 2)   g_denom[idx] = 0.f;

    int n = idx >> 7, ch = idx & 127;
    const float* xv = x + n * 8;
    float sl = bl[ch], sr = br[ch];
    #pragma unroll
    for (int i = 0; i < 8; i++) {
        float xi = xv[i];
        sl += xi * Wl[ch * 8 + i];
        sr += xi * Wr[ch * 8 + i];
    }
    g_xl[idx] = __float2half(sl);
    g_xr[idx] = __float2half(sr);
}

// -------- 2. fused logits + exp + denom + unnormalized message scatter ------
__global__ void k_logits(const int* __restrict__ ei,
                         const float* __restrict__ ea,
                         const float* __restrict__ We,
                         const float* __restrict__ att, int E) {
    int warp = (blockIdx.x * blockDim.x + threadIdx.x) >> 5;
    int lane = threadIdx.x & 31;
    int e0 = warp * 4;
    if (e0 >= E) return;

    float4 at   = ((const float4*)att)[lane];
    float4 we01 = ((const float4*)We)[2 * lane];
    float4 we23 = ((const float4*)We)[2 * lane + 1];

    int src[4], dst[4];
    float2 eav[4];
    #pragma unroll
    for (int j = 0; j < 4; j++) {
        int e = min(e0 + j, E - 1);
        src[j] = ei[e];
        dst[j] = ei[E + e];
        eav[j] = ((const float2*)ea)[e];
    }
    float4 a[4], b[4];
    #pragma unroll
    for (int j = 0; j < 4; j++) a[j] = ld_half4(g_xl, src[j] * 32 + lane);
    #pragma unroll
    for (int j = 0; j < 4; j++) b[j] = ld_half4(g_xr, dst[j] * 32 + lane);

    float s[4];
    #pragma unroll
    for (int j = 0; j < 4; j++) {
        float e_0 = we01.x * eav[j].x + we01.y * eav[j].y;
        float e_1 = we01.z * eav[j].x + we01.w * eav[j].y;
        float e_2 = we23.x * eav[j].x + we23.y * eav[j].y;
        float e_3 = we23.z * eav[j].x + we23.w * eav[j].y;
        float z, acc = 0.f;
        z = a[j].x + b[j].x + e_0; z = z > 0.f ? z : NEG_SLOPE * z; acc += z * at.x;
        z = a[j].y + b[j].y + e_1; z = z > 0.f ? z : NEG_SLOPE * z; acc += z * at.y;
        z = a[j].z + b[j].z + e_2; z = z > 0.f ? z : NEG_SLOPE * z; acc += z * at.z;
        z = a[j].w + b[j].w + e_3; z = z > 0.f ? z : NEG_SLOPE * z; acc += z * at.w;
        s[j] = acc;
    }
    #pragma unroll
    for (int o = 8; o >= 1; o >>= 1) {
        #pragma unroll
        for (int j = 0; j < 4; j++)
            s[j] += __shfl_xor_sync(0xffffffffu, s[j], o, 16);
    }
    float p[4], pd[4];
    #pragma unroll
    for (int j = 0; j < 4; j++) p[j] = __expf(s[j]);  // |logit| small: no max-sub
    #pragma unroll
    for (int j = 0; j < 4; j++) pd[j] = __shfl_down_sync(0xffffffffu, p[j], 16);

    // epilogue distributed across lanes 0-3 (one edge each)
    if (lane < 4) {
        float myp  = (lane == 0) ? p[0]  : (lane == 1) ? p[1]  : (lane == 2) ? p[2]  : p[3];
        float mypd = (lane == 0) ? pd[0] : (lane == 1) ? pd[1] : (lane == 2) ? pd[2] : pd[3];
        int   myd  = (lane == 0) ? dst[0]: (lane == 1) ? dst[1]: (lane == 2) ? dst[2]: dst[3];
        int e = e0 + lane;
        if (e < E) {
            ((float2*)g_expl)[e] = make_float2(myp, mypd);
            red_add_v2(&g_denom[2 * myd], myp, mypd);
        }
    }
    #pragma unroll
    for (int j = 0; j < 4; j++) {
        if (e0 + j < E) {
            float4 m = a[j];
            m.x *= p[j]; m.y *= p[j]; m.z *= p[j]; m.w *= p[j];
            red_add_v4(&g_hacc[dst[j] * HC + lane * 4], m);
        }
    }
}

// -------- 3. register-tiled node GEMM: 64 nodes/block, 4x4 tile/thread ------
// g_hw = half( (relu(hacc/denom + bias) @ gcn_W.T) * 1{denom>0} )
#define NHB 64
#define WP  68
__global__ void k_node_hw(const float* __restrict__ gat_bias,
                          const float* __restrict__ gcn_W, int N) {
    __shared__ __align__(16) float Wsh[64 * WP];
    __shared__ __align__(16) float hsh[64 * WP];
    __shared__ float inv0[NHB], inv1[NHB], dsh[NHB];
    __shared__ float bsh[HC];
    int t = threadIdx.x;                 // 256
    int base = blockIdx.x * NHB;

    if (t < HC) bsh[t] = gat_bias[t];
    if (t < NHB) {
        int n = base + t;
        if (n < N) {
            float2 dn = ((const float2*)g_denom)[n];
            inv0[t] = dn.x > 0.f ? __fdividef(1.f, dn.x) : 0.f;
            inv1[t] = dn.y > 0.f ? __fdividef(1.f, dn.y) : 0.f;
            dsh[t]  = dn.x > 0.f ? 1.f : 0.f;   // indicator(n has in-edges)
        } else { inv0[t] = 0.f; inv1[t] = 0.f; dsh[t] = 0.f; }
    }
    __syncthreads();

    int tx = t & 15;          // col group: cols 4tx..4tx+3
    int ty = t >> 4;          // node group: nodes 4ty..4ty+3
    float acc[4][4];
    #pragma unroll
    for (int i = 0; i < 4; i++)
        #pragma unroll
        for (int j = 0; j < 4; j++) acc[i][j] = 0.f;

    #pragma unroll
    for (int ph = 0; ph < 2; ph++) {
        {
            int k = t & 63, cb = t >> 6;
            #pragma unroll
            for (int j = 0; j < 16; j++) {
                int c = cb + j * 4;
                Wsh[k * WP + c] = gcn_W[c * HC + ph * 64 + k];
            }
        }
        {
            int c = t & 63, nb = t >> 6;
            #pragma unroll
            for (int j = 0; j < 16; j++) {
                int nl = nb + j * 4;
                int n = base + nl;
                float v = 0.f;
                if (n < N) {
                    float iv = ph ? inv1[nl] : inv0[nl];
                    v = fmaxf(g_hacc[n * HC + ph * 64 + c] * iv + bsh[ph * 64 + c], 0.f);
                }
                hsh[c * WP + nl] = v;
            }
        }
        __syncthreads();
        #pragma unroll 4
        for (int k = 0; k < 64; k++) {
            float4 w = *(const float4*)&Wsh[k * WP + tx * 4];
            float4 h = *(const float4*)&hsh[k * WP + ty * 4];
            acc[0][0] += h.x * w.x; acc[0][1] += h.x * w.y;
            acc[0][2] += h.x * w.z; acc[0][3] += h.x * w.w;
            acc[1][0] += h.y * w.x; acc[1][1] += h.y * w.y;
            acc[1][2] += h.y * w.z; acc[1][3] += h.y * w.w;
            acc[2][0] += h.z * w.x; acc[2][1] += h.z * w.y;
            acc[2][2] += h.z * w.z; acc[2][3] += h.z * w.w;
            acc[3][0] += h.w * w.x; acc[3][1] += h.w * w.y;
            acc[3][2] += h.w * w.z; acc[3][3] += h.w * w.w;
        }
        __syncthreads();
    }
    #pragma unroll
    for (int i = 0; i < 4; i++) {
        int nl = ty * 4 + i;
        int n = base + nl;
        if (n < N) {
            float di = dsh[nl];          // indicator fold (src-side GCN norm)
            __half2 o01 = __floats2half2_rn(acc[i][0] * di, acc[i][1] * di);
            __half2 o23 = __floats2half2_rn(acc[i][2] * di, acc[i][3] * di);
            uint2 raw;
            raw.x = *reinterpret_cast<unsigned int*>(&o01);
            raw.y = *reinterpret_cast<unsigned int*>(&o23);
            ((uint2*)g_hw)[n * 16 + tx] = raw;
        }
    }
}

// -------- 4. fused alpha + GCN edge scatter --------
// alpha = expl/denom[dst]; ew = mean; h2acc[dst] += ew·hw[src]  (fp32 accum)
__global__ void k_gcn_edge(const int* __restrict__ ei,
                           float* __restrict__ alpha_out, int E) {
    int warp = (blockIdx.x * blockDim.x + threadIdx.x) >> 5;
    int lane = threadIdx.x & 31;
    int half = lane >> 4;
    int l    = lane & 15;
    int e0 = warp * 8 + half;
    if (e0 >= E) return;

    int src[4], dst[4];
    #pragma unroll
    for (int j = 0; j < 4; j++) {
        int e = min(e0 + 2 * j, E - 1);
        src[j] = ei[e];
        dst[j] = ei[E + e];
    }
    float2 pe[4];
    #pragma unroll
    for (int j = 0; j < 4; j++) pe[j] = ((const float2*)g_expl)[min(e0 + 2 * j, E - 1)];
    float2 dn[4];
    #pragma unroll
    for (int j = 0; j < 4; j++) dn[j] = ((const float2*)g_denom)[dst[j]];

    float nv[4];
    #pragma unroll
    for (int j = 0; j < 4; j++) {
        float a0 = __fdividef(pe[j].x, dn[j].x);
        float a1 = __fdividef(pe[j].y, dn[j].y);
        nv[j] = 0.5f * (a0 + a1);
        int e = e0 + 2 * j;
        if (l == 0 && e < E)
            ((float2*)alpha_out)[e] = make_float2(a0, a1);
    }
    float4 v[4];
    #pragma unroll
    for (int j = 0; j < 4; j++)
        v[j] = ld_half4(g_hw, src[j] * 16 + l);
    #pragma unroll
    for (int j = 0; j < 4; j++) {
        if (e0 + 2 * j < E) {
            float4 m = v[j];
            m.x *= nv[j]; m.y *= nv[j]; m.z *= nv[j]; m.w *= nv[j];
            red_add_v4(&g_h2acc[dst[j] * HID + l * 4], m);
        }
    }
}

// -------- 5. per-node output --------
__global__ void k_node_out(const float* __restrict__ gcn_b,
                           const float* __restrict__ out_W,
                           const float* __restrict__ out_b,
                           float* __restrict__ out, int N) {
    int t = blockIdx.x * blockDim.x + threadIdx.x;
    int n = t >> 5;
    if (n >= N) return;
    int lane = t & 31;
    float2 hv = ((const float2*)g_h2acc)[n * 32 + lane];
    float h0 = fmaxf(hv.x + gcn_b[2 * lane],     0.f);
    float h1 = fmaxf(hv.y + gcn_b[2 * lane + 1], 0.f);
    float s0 = h0 * out_W[2 * lane]      + h1 * out_W[2 * lane + 1];
    float s1 = h0 * out_W[64 + 2 * lane] + h1 * out_W[64 + 2 * lane + 1];
    #pragma unroll
    for (int o = 16; o >= 1; o >>= 1) {
        s0 += __shfl_down_sync(0xffffffffu, s0, o);
        s1 += __shfl_down_sync(0xffffffffu, s1, o);
    }
    if (lane == 0) {
        out[2 * n]     = s0 + out_b[0];
        out[2 * n + 1] = s1 + out_b[1];
    }
}

extern "C" void kernel_launch(void* const* d_in, const int* in_sizes, int n_in,
                              void* d_out, int out_size) {
    const float* x        = (const float*)d_in[0];
    const float* ea       = (const float*)d_in[1];
    const int*   ei       = (const int*)d_in[2];   // int32 (JAX x64 disabled)
    const float* Wl       = (const float*)d_in[3];
    const float* bl       = (const float*)d_in[4];
    const float* Wr       = (const float*)d_in[5];
    const float* br       = (const float*)d_in[6];
    const float* We       = (const float*)d_in[7];
    const float* att      = (const float*)d_in[8];
    const float* gat_bias = (const float*)d_in[9];
    const float* gcn_W    = (const float*)d_in[10];
    const float* gcn_b    = (const float*)d_in[11];
    const float* out_W    = (const float*)d_in[12];
    const float* out_b    = (const float*)d_in[13];

    int N = in_sizes[0] / 8;     // IN=8
    int E = in_sizes[1] / 2;     // ED=2

    float* out       = (float*)d_out;
    float* alpha_out = (float*)d_out + (size_t)N * 2;

    const int NT = 256;
    int warpsL = (E + 3) / 4;   // 4 edges/warp
    int warpsG = (E + 7) / 8;   // 8 edges/warp
    k_proj<<<(N * HC + NT - 1) / NT, NT>>>(x, Wl, bl, Wr, br, N);
    k_logits<<<(int)(((size_t)warpsL * 32 + NT - 1) / NT), NT>>>(ei, ea, We, att, E);
    k_node_hw<<<(N + NHB - 1) / NHB, 256>>>(gat_bias, gcn_W, N);
    k_gcn_edge<<<(int)(((size_t)warpsG * 32 + NT - 1) / NT), NT>>>(ei, alpha_out, E);
    k_node_out<<<(int)(((size_t)N * 32 + NT - 1) / NT), NT>>>(gcn_b, out_W, out_b, out, N);
}

// round 16
// speedup vs baseline: 1.3781x; 1.0303x over previous
#include <cuda_runtime.h>
#include <cuda_fp16.h>
#include <cuda_bf16.h>

// GNN_Attention: N=50000, E=800000, IN=8, ED=2, H=2, C=64, HID=64, OUT=2
#define MAXN 50000
#define MAXE 800000
#define HC   128
#define HID  64
#define NEG_SLOPE 0.2f

// -------- static device scratch --------
__device__ __align__(16) __half g_xl[MAXN * HC];   // logit operand (fp16)
__device__ __align__(16) __half g_xr[MAXN * HC];   // logit operand (fp16)
__device__ __align__(16) __half g_xh[MAXN * 8];    // fp16 copy of x (message moment)
__device__ __align__(16) float  g_expl[MAXE * 2];
__device__ __align__(16) float  g_denom[MAXN * 2];
__device__ __align__(16) float  g_t[MAXN * 16];    // Σ p_h·x[src]: [n][h][i], fp32
__device__ __align__(16) __half g_hw[MAXN * HID];  // (h @ gcn_W.T) * indicator
__device__ __align__(16) float  g_h2acc[MAXN * HID];

__device__ __forceinline__ void red_add_v4(float* p, float4 v) {
    asm volatile("red.global.add.v4.f32 [%0], {%1,%2,%3,%4};"
                 :: "l"(p), "f"(v.x), "f"(v.y), "f"(v.z), "f"(v.w)
                 : "memory");
}
__device__ __forceinline__ void red_add_v2(float* p, float a, float b) {
    asm volatile("red.global.add.v2.f32 [%0], {%1,%2};"
                 :: "l"(p), "f"(a), "f"(b)
                 : "memory");
}
__device__ __forceinline__ float4 ld_half4(const __half* base, int idx8) {
    uint2 raw = ((const uint2*)base)[idx8];
    __half2 h01 = *reinterpret_cast<__half2*>(&raw.x);
    __half2 h23 = *reinterpret_cast<__half2*>(&raw.y);
    float2 f01 = __half22float2(h01);
    float2 f23 = __half22float2(h23);
    return make_float4(f01.x, f01.y, f23.x, f23.y);
}

// -------- 1. node projections + zero accumulators + fp16 x copy --------
__global__ void k_proj(const float* __restrict__ x,
                       const float* __restrict__ Wl, const float* __restrict__ bl,
                       const float* __restrict__ Wr, const float* __restrict__ br,
                       int N) {
    int idx = blockIdx.x * blockDim.x + threadIdx.x;
    if (idx >= N * HC) return;
    if (idx < N * 16)  g_t[idx]     = 0.f;
    if (idx < N * HID) g_h2acc[idx] = 0.f;
    if (idx < N * 2)   g_denom[idx] = 0.f;
    if (idx < N * 8)   g_xh[idx]    = __float2half(x[idx]);

    int n = idx >> 7, ch = idx & 127;
    const float* xv = x + n * 8;
    float sl = bl[ch], sr = br[ch];
    #pragma unroll
    for (int i = 0; i < 8; i++) {
        float xi = xv[i];
        sl += xi * Wl[ch * 8 + i];
        sr += xi * Wr[ch * 8 + i];
    }
    g_xl[idx] = __float2half(sl);
    g_xr[idx] = __float2half(sr);
}

// -------- 2. fused logits + exp + denom + 8-dim moment scatter --------
// msg is linear in x: hacc = t@Wl.T + denom*bl, so scatter only
// t[dst][h] += p_h * x[src]  (4 red.v4 lanes/edge instead of 32).
__global__ void k_logits(const int* __restrict__ ei,
                         const float* __restrict__ ea,
                         const float* __restrict__ We,
                         const float* __restrict__ att, int E) {
    int warp = (blockIdx.x * blockDim.x + threadIdx.x) >> 5;
    int lane = threadIdx.x & 31;
    int e0 = warp * 4;
    if (e0 >= E) return;

    float4 at   = ((const float4*)att)[lane];
    float4 we01 = ((const float4*)We)[2 * lane];
    float4 we23 = ((const float4*)We)[2 * lane + 1];

    int src[4], dst[4];
    float2 eav[4];
    #pragma unroll
    for (int j = 0; j < 4; j++) {
        int e = min(e0 + j, E - 1);
        src[j] = ei[e];
        dst[j] = ei[E + e];
        eav[j] = ((const float2*)ea)[e];
    }
    float4 a[4], b[4];
    #pragma unroll
    for (int j = 0; j < 4; j++) a[j] = ld_half4(g_xl, src[j] * 32 + lane);
    #pragma unroll
    for (int j = 0; j < 4; j++) b[j] = ld_half4(g_xr, dst[j] * 32 + lane);

    float s[4];
    #pragma unroll
    for (int j = 0; j < 4; j++) {
        float e_0 = we01.x * eav[j].x + we01.y * eav[j].y;
        float e_1 = we01.z * eav[j].x + we01.w * eav[j].y;
        float e_2 = we23.x * eav[j].x + we23.y * eav[j].y;
        float e_3 = we23.z * eav[j].x + we23.w * eav[j].y;
        float z, acc = 0.f;
        z = a[j].x + b[j].x + e_0; z = z > 0.f ? z : NEG_SLOPE * z; acc += z * at.x;
        z = a[j].y + b[j].y + e_1; z = z > 0.f ? z : NEG_SLOPE * z; acc += z * at.y;
        z = a[j].z + b[j].z + e_2; z = z > 0.f ? z : NEG_SLOPE * z; acc += z * at.z;
        z = a[j].w + b[j].w + e_3; z = z > 0.f ? z : NEG_SLOPE * z; acc += z * at.w;
        s[j] = acc;
    }
    #pragma unroll
    for (int o = 8; o >= 1; o >>= 1) {
        #pragma unroll
        for (int j = 0; j < 4; j++)
            s[j] += __shfl_xor_sync(0xffffffffu, s[j], o, 16);
    }
    float p[4], pd[4];
    #pragma unroll
    for (int j = 0; j < 4; j++) p[j] = __expf(s[j]);  // |logit| small: no max-sub
    #pragma unroll
    for (int j = 0; j < 4; j++) pd[j] = __shfl_down_sync(0xffffffffu, p[j], 16);
    // lanes 0-15 now hold: p[j] = head0 exp, pd[j] = head1 exp

    // expl + denom epilogue: lanes 0-3, one edge each
    if (lane < 4) {
        float myp  = (lane == 0) ? p[0]  : (lane == 1) ? p[1]  : (lane == 2) ? p[2]  : p[3];
        float mypd = (lane == 0) ? pd[0] : (lane == 1) ? pd[1] : (lane == 2) ? pd[2] : pd[3];
        int   myd  = (lane == 0) ? dst[0]: (lane == 1) ? dst[1]: (lane == 2) ? dst[2]: dst[3];
        int e = e0 + lane;
        if (e < E) {
            ((float2*)g_expl)[e] = make_float2(myp, mypd);
            red_add_v2(&g_denom[2 * myd], myp, mypd);
        }
    }
    // moment scatter: lanes 0-15, lane = 4j+q; q: {head=q>>1, xpart=q&1}
    if (lane < 16) {
        int j = lane >> 2, q = lane & 3;
        if (e0 + j < E) {
            int   msrc = (j == 0) ? src[0] : (j == 1) ? src[1] : (j == 2) ? src[2] : src[3];
            int   mdst = (j == 0) ? dst[0] : (j == 1) ? dst[1] : (j == 2) ? dst[2] : dst[3];
            float ph0  = (j == 0) ? p[0]   : (j == 1) ? p[1]   : (j == 2) ? p[2]   : p[3];
            float ph1  = (j == 0) ? pd[0]  : (j == 1) ? pd[1]  : (j == 2) ? pd[2]  : pd[3];
            float ps = (q < 2) ? ph0 : ph1;
            uint4 raw = ((const uint4*)g_xh)[msrc];
            unsigned w0 = (q & 1) ? raw.z : raw.x;
            unsigned w1 = (q & 1) ? raw.w : raw.y;
            __half2 h01 = *reinterpret_cast<__half2*>(&w0);
            __half2 h23 = *reinterpret_cast<__half2*>(&w1);
            float2 f01 = __half22float2(h01);
            float2 f23 = __half22float2(h23);
            float4 v = make_float4(ps * f01.x, ps * f01.y, ps * f23.x, ps * f23.y);
            red_add_v4(&g_t[mdst * 16 + (q >> 1) * 8 + (q & 1) * 4], v);
        }
    }
}

// -------- 3. node GEMM: reconstruct h from t, then h @ gcn_W.T --------
// hacc_ch = t[h]·Wl[ch] + denom_h·bl[ch];  v = hacc*inv + bias → relu
//         = (t·Wl_row)*inv + ind·bl[ch] + bias[ch]
#define NHB 64
#define WP  68
__global__ void k_node_hw(const float* __restrict__ gat_bias,
                          const float* __restrict__ gcn_W,
                          const float* __restrict__ Wl,
                          const float* __restrict__ bl, int N) {
    __shared__ __align__(16) float Wsh[64 * WP];    // 17.4 KB (gcn_W slice, transposed)
    __shared__ __align__(16) float hsh[64 * WP];    // 17.4 KB
    __shared__ float Wlsh[HC * 9];                  // 4.6 KB (Wl rows, pad 9)
    __shared__ __align__(16) float tsh[NHB * 16];   // 4 KB
    __shared__ float inv0[NHB], inv1[NHB], dsh[NHB];
    __shared__ float bsh[HC], blsh[HC];
    int t = threadIdx.x;                 // 256
    int base = blockIdx.x * NHB;

    if (t < HC) { bsh[t] = gat_bias[t]; blsh[t] = bl[t]; }
    for (int i = t; i < HC * 8; i += 256) {
        int row = i >> 3, col = i & 7;
        Wlsh[row * 9 + col] = Wl[i];
    }
    for (int i = t; i < NHB * 16; i += 256) {
        int gi = base * 16 + i;
        tsh[i] = (gi < N * 16) ? g_t[gi] : 0.f;
    }
    if (t < NHB) {
        int n = base + t;
        if (n < N) {
            float2 dn = ((const float2*)g_denom)[n];
            inv0[t] = dn.x > 0.f ? __fdividef(1.f, dn.x) : 0.f;
            inv1[t] = dn.y > 0.f ? __fdividef(1.f, dn.y) : 0.f;
            dsh[t]  = dn.x > 0.f ? 1.f : 0.f;   // indicator(n has in-edges)
        } else { inv0[t] = 0.f; inv1[t] = 0.f; dsh[t] = 0.f; }
    }
    __syncthreads();

    int tx = t & 15;          // col group: cols 4tx..4tx+3
    int ty = t >> 4;          // node group: nodes 4ty..4ty+3
    float acc[4][4];
    #pragma unroll
    for (int i = 0; i < 4; i++)
        #pragma unroll
        for (int j = 0; j < 4; j++) acc[i][j] = 0.f;

    #pragma unroll
    for (int ph = 0; ph < 2; ph++) {
        {
            int k = t & 63, cb = t >> 6;
            #pragma unroll
            for (int j = 0; j < 16; j++) {
                int c = cb + j * 4;
                Wsh[k * WP + c] = gcn_W[c * HC + ph * 64 + k];
            }
        }
        {
            int c = t & 63, nb = t >> 6;
            int ch = ph * 64 + c;
            #pragma unroll
            for (int j = 0; j < 16; j++) {
                int nl = nb + j * 4;
                float iv = ph ? inv1[nl] : inv0[nl];
                const float* tp = &tsh[nl * 16 + ph * 8];
                const float* wp = &Wlsh[ch * 9];
                float td = tp[0] * wp[0] + tp[1] * wp[1] + tp[2] * wp[2] + tp[3] * wp[3]
                         + tp[4] * wp[4] + tp[5] * wp[5] + tp[6] * wp[6] + tp[7] * wp[7];
                hsh[c * WP + nl] =
                    fmaxf(td * iv + dsh[nl] * blsh[ch] + bsh[ch], 0.f);
            }
        }
        __syncthreads();
        #pragma unroll 4
        for (int k = 0; k < 64; k++) {
            float4 w = *(const float4*)&Wsh[k * WP + tx * 4];
            float4 h = *(const float4*)&hsh[k * WP + ty * 4];
            acc[0][0] += h.x * w.x; acc[0][1] += h.x * w.y;
            acc[0][2] += h.x * w.z; acc[0][3] += h.x * w.w;
            acc[1][0] += h.y * w.x; acc[1][1] += h.y * w.y;
            acc[1][2] += h.y * w.z; acc[1][3] += h.y * w.w;
            acc[2][0] += h.z * w.x; acc[2][1] += h.z * w.y;
            acc[2][2] += h.z * w.z; acc[2][3] += h.z * w.w;
            acc[3][0] += h.w * w.x; acc[3][1] += h.w * w.y;
            acc[3][2] += h.w * w.z; acc[3][3] += h.w * w.w;
        }
        __syncthreads();
    }
    #pragma unroll
    for (int i = 0; i < 4; i++) {
        int nl = ty * 4 + i;
        int n = base + nl;
        if (n < N) {
            float di = dsh[nl];          // indicator fold (src-side GCN norm)
            __half2 o01 = __floats2half2_rn(acc[i][0] * di, acc[i][1] * di);
            __half2 o23 = __floats2half2_rn(acc[i][2] * di, acc[i][3] * di);
            uint2 raw;
            raw.x = *reinterpret_cast<unsigned int*>(&o01);
            raw.y = *reinterpret_cast<unsigned int*>(&o23);
            ((uint2*)g_hw)[n * 16 + tx] = raw;
        }
    }
}

// -------- 4. fused alpha + GCN edge scatter --------
__global__ void k_gcn_edge(const int* __restrict__ ei,
                           float* __restrict__ alpha_out, int E) {
    int warp = (blockIdx.x * blockDim.x + threadIdx.x) >> 5;
    int lane = threadIdx.x & 31;
    int half = lane >> 4;
    int l    = lane & 15;
    int e0 = warp * 8 + half;
    if (e0 >= E) return;

    int src[4], dst[4];
    #pragma unroll
    for (int j = 0; j < 4; j++) {
        int e = min(e0 + 2 * j, E - 1);
        src[j] = ei[e];
        dst[j] = ei[E + e];
    }
    float2 pe[4];
    #pragma unroll
    for (int j = 0; j < 4; j++) pe[j] = ((const float2*)g_expl)[min(e0 + 2 * j, E - 1)];
    float2 dn[4];
    #pragma unroll
    for (int j = 0; j < 4; j++) dn[j] = ((const float2*)g_denom)[dst[j]];

    float nv[4];
    #pragma unroll
    for (int j = 0; j < 4; j++) {
        float a0 = __fdividef(pe[j].x, dn[j].x);
        float a1 = __fdividef(pe[j].y, dn[j].y);
        nv[j] = 0.5f * (a0 + a1);
        int e = e0 + 2 * j;
        if (l == 0 && e < E)
            ((float2*)alpha_out)[e] = make_float2(a0, a1);
    }
    float4 v[4];
    #pragma unroll
    for (int j = 0; j < 4; j++)
        v[j] = ld_half4(g_hw, src[j] * 16 + l);
    #pragma unroll
    for (int j = 0; j < 4; j++) {
        if (e0 + 2 * j < E) {
            float4 m = v[j];
            m.x *= nv[j]; m.y *= nv[j]; m.z *= nv[j]; m.w *= nv[j];
            red_add_v4(&g_h2acc[dst[j] * HID + l * 4], m);
        }
    }
}

// -------- 5. per-node output --------
__global__ void k_node_out(const float* __restrict__ gcn_b,
                           const float* __restrict__ out_W,
                           const float* __restrict__ out_b,
                           float* __restrict__ out, int N) {
    int t = blockIdx.x * blockDim.x + threadIdx.x;
    int n = t >> 5;
    if (n >= N) return;
    int lane = t & 31;
    float2 hv = ((const float2*)g_h2acc)[n * 32 + lane];
    float h0 = fmaxf(hv.x + gcn_b[2 * lane],     0.f);
    float h1 = fmaxf(hv.y + gcn_b[2 * lane + 1], 0.f);
    float s0 = h0 * out_W[2 * lane]      + h1 * out_W[2 * lane + 1];
    float s1 = h0 * out_W[64 + 2 * lane] + h1 * out_W[64 + 2 * lane + 1];
    #pragma unroll
    for (int o = 16; o >= 1; o >>= 1) {
        s0 += __shfl_down_sync(0xffffffffu, s0, o);
        s1 += __shfl_down_sync(0xffffffffu, s1, o);
    }
    if (lane == 0) {
        out[2 * n]     = s0 + out_b[0];
        out[2 * n + 1] = s1 + out_b[1];
    }
}

extern "C" void kernel_launch(void* const* d_in, const int* in_sizes, int n_in,
                              void* d_out, int out_size) {
    const float* x        = (const float*)d_in[0];
    const float* ea       = (const float*)d_in[1];
    const int*   ei       = (const int*)d_in[2];   // int32 (JAX x64 disabled)
    const float* Wl       = (const float*)d_in[3];
    const float* bl       = (const float*)d_in[4];
    const float* Wr       = (const float*)d_in[5];
    const float* br       = (const float*)d_in[6];
    const float* We       = (const float*)d_in[7];
    const float* att      = (const float*)d_in[8];
    const float* gat_bias = (const float*)d_in[9];
    const float* gcn_W    = (const float*)d_in[10];
    const float* gcn_b    = (const float*)d_in[11];
    const float* out_W    = (const float*)d_in[12];
    const float* out_b    = (const float*)d_in[13];

    int N = in_sizes[0] / 8;     // IN=8
    int E = in_sizes[1] / 2;     // ED=2

    float* out       = (float*)d_out;
    float* alpha_out = (float*)d_out + (size_t)N * 2;

    const int NT = 256;
    int warpsL = (E + 3) / 4;   // 4 edges/warp
    int warpsG = (E + 7) / 8;   // 8 edges/warp
    k_proj<<<(N * HC + NT - 1) / NT, NT>>>(x, Wl, bl, Wr, br, N);
    k_logits<<<(int)(((size_t)warpsL * 32 + NT - 1) / NT), NT>>>(ei, ea, We, att, E);
    k_node_hw<<<(N + NHB - 1) / NHB, 256>>>(gat_bias, gcn_W, Wl, bl, N);
    k_gcn_edge<<<(int)(((size_t)warpsG * 32 + NT - 1) / NT), NT>>>(ei, alpha_out, E);
    k_node_out<<<(int)(((size_t)N * 32 + NT - 1) / NT), NT>>>(gcn_b, out_W, out_b, out, N);
}